// round 15
// baseline (speedup 1.0000x reference)
#include <cuda_runtime.h>
#include <cuda_fp16.h>
#include <cstdint>

// ---------------- problem constants ----------------
#define T_TOK 2048
#define H_DIM 2048
#define F_DIM 5632
#define E_NUM 8
#define K_TOP 2
#define F2    (2 * F_DIM)

// ---------------- tiling ----------------
#define BM 128
#define BK 64
#define ROWB 144                      // fp16 row pitch bytes (72 halves)
#define TILE16 (BM * ROWB)            // 18432
#define STAGE_SZ (2 * TILE16)         // A16 + B16 = 36864
#define OFF_B TILE16
#define MAXROWS  5120
#define MAXTILES 40

// ---------------- device scratch ----------------
__device__ __half g_xg [(size_t)MAXROWS * H_DIM];
__device__ __half g_act[(size_t)MAXROWS * F_DIM];
__device__ int   g_tok[MAXROWS];
__device__ float g_wt [MAXROWS];
__device__ int   g_tile_expert[MAXTILES];

// ---------------- helpers ----------------
__device__ __forceinline__ uint32_t smem_u32(const void* p) {
    uint32_t a;
    asm("{ .reg .u64 t; cvta.to.shared.u64 t, %1; cvt.u32.u64 %0, t; }" : "=r"(a) : "l"(p));
    return a;
}
__device__ __forceinline__ void cpa16(uint32_t dst, const void* src) {
    asm volatile("cp.async.cg.shared.global [%0], [%1], 16;" :: "r"(dst), "l"(src));
}
#define CPA_COMMIT() asm volatile("cp.async.commit_group;" ::: "memory")
#define CPA_WAIT0()  asm volatile("cp.async.wait_group 0;" ::: "memory")

__device__ __forceinline__ void ldm4(uint32_t* r, uint32_t addr) {
    asm volatile("ldmatrix.sync.aligned.m8n8.x4.shared.b16 {%0,%1,%2,%3}, [%4];"
                 : "=r"(r[0]), "=r"(r[1]), "=r"(r[2]), "=r"(r[3]) : "r"(addr));
}
__device__ __forceinline__ void mma16816(float* d, const uint32_t* a, const uint32_t* b) {
    asm("mma.sync.aligned.m16n8k16.row.col.f32.f16.f16.f32 "
        "{%0,%1,%2,%3}, {%4,%5,%6,%7}, {%8,%9}, {%0,%1,%2,%3};\n"
        : "+f"(d[0]), "+f"(d[1]), "+f"(d[2]), "+f"(d[3])
        : "r"(a[0]), "r"(a[1]), "r"(a[2]), "r"(a[3]),
          "r"(b[0]), "r"(b[1]));
}
__device__ __forceinline__ uint32_t pack_h2(float a, float b) {
    __half2 h = __floats2half2_rn(a, b);
    return *(uint32_t*)&h;
}

// ---------------- routing ----------------
__global__ void k_zero(float* __restrict__ out) {
    int tid = blockIdx.x * blockDim.x + threadIdx.x;
    int nt  = gridDim.x * blockDim.x;
    for (int i = tid; i < T_TOK * H_DIM; i += nt) out[i] = 0.0f;
}
__global__ void k_route(const int* __restrict__ sel, const float* __restrict__ rw) {
    __shared__ int cnt[E_NUM];
    __shared__ int cur[E_NUM];
    const int tid = threadIdx.x;
    if (tid < E_NUM) cnt[tid] = 0;
    for (int i = tid; i < MAXROWS; i += blockDim.x) { g_tok[i] = -1; g_wt[i] = 0.0f; }
    __syncthreads();
    for (int i = tid; i < T_TOK * K_TOP; i += blockDim.x) atomicAdd(&cnt[sel[i]], 1);
    __syncthreads();
    if (tid == 0) {
        for (int t = 0; t < MAXTILES; ++t) g_tile_expert[t] = -1;
        int off = 0;
        for (int e = 0; e < E_NUM; ++e) {
            cur[e] = off;
            int tiles = (cnt[e] + BM - 1) / BM;
            for (int j = 0; j < tiles; ++j) g_tile_expert[off / BM + j] = e;
            off += tiles * BM;
        }
    }
    __syncthreads();
    for (int i = tid; i < T_TOK * K_TOP; i += blockDim.x) {
        int e = sel[i];
        int pos = atomicAdd(&cur[e], 1);
        g_tok[pos] = i / K_TOP;
        g_wt[pos]  = rw[i];
    }
}
__global__ void k_gather(const float* __restrict__ X) {
    const int row = blockIdx.x;
    if (g_tile_expert[row >> 7] < 0) return;
    const int tok = g_tok[row];
    uint2* dst = (uint2*)(g_xg + (size_t)row * H_DIM);
    if (tok >= 0) {
        const float4* src = (const float4*)(X + (size_t)tok * H_DIM);
        for (int i = threadIdx.x; i < H_DIM / 4; i += blockDim.x) {
            float4 v = src[i];
            dst[i] = make_uint2(pack_h2(v.x, v.y), pack_h2(v.z, v.w));
        }
    } else {
        for (int i = threadIdx.x; i < H_DIM / 4; i += blockDim.x)
            dst[i] = make_uint2(0u, 0u);
    }
}

// ---------------- fp16 tensor GEMM: 256 thr, 8 warps of 64x32 ----------------
// 2 CTAs/SM -> 16 warps/SM (4/SMSP). Clean inner loop (LDSM+HMMA only);
// B staged via quarter-chunk LDG fp32 -> reg -> fp16 STS between ks steps.
// grid: x = tile_m (fast, L2 B reuse), y = tile_n, z = K-split (MODE 2)
template <int MODE>
__global__ void __launch_bounds__(256, 2)
k_gemm(const float* __restrict__ W, float* __restrict__ out) {
    constexpr int KD     = (MODE == 1) ? H_DIM : F_DIM;
    constexpr int KSPLIT = (MODE == 1) ? 1 : 2;
    constexpr int NC     = KD / BK / KSPLIT;   // 32 or 44

    const int tile_m = blockIdx.x;
    const int tile_n = blockIdx.y;
    const int koff0  = (MODE == 2) ? (int)blockIdx.z * (KD / KSPLIT) : 0;
    const int e = g_tile_expert[tile_m];
    if (e < 0) return;

    extern __shared__ char smem[];
    const uint32_t sb = smem_u32(smem);

    const int tid  = threadIdx.x;
    const int lane = tid & 31;
    const int warp = tid >> 5;
    const int wm   = warp & 1;                 // 2 warps along M (64 rows)
    const int wn   = warp >> 1;                // 4 warps along N (32 cols)

    // ---- A cp.async: 1024 granules, 4/thread; row = j*32 + (tid>>3), q = tid&7
    const __half* Aptr = (((MODE == 1) ? g_xg : g_act) + (size_t)tile_m * BM * KD)
                         + (size_t)(tid >> 3) * KD + (tid & 7) * 8 + koff0;
    const uint32_t doffA = (uint32_t)((tid >> 3) * ROWB + (tid & 7) * 16);

    // ---- B fp32 LDG quarter-chunks: 512 granules/quarter, 2/thread
    const float* Bbase;
    const float* Bup = nullptr;
    if (MODE == 1) {
        Bbase = W + (size_t)e * F2 * H_DIM + (size_t)tile_n * 64 * H_DIM;   // gate rows 0-63
        Bup   = Bbase + (size_t)F_DIM * H_DIM;                              // up rows 64-127
    } else {
        Bbase = W + (size_t)e * H_DIM * F_DIM + (size_t)tile_n * BM * F_DIM;
    }

    float4 breg[2][2];
    auto ldQ = [&](int c, int q, int buf) {
        const int koff = koff0 + c * BK;
#pragma unroll
        for (int j = 0; j < 2; ++j) {
            const int idx = j * 256 + tid;
            const int row = q * 32 + (idx >> 4);
            const float* src = (MODE == 1)
                ? ((row < 64) ? Bbase + (size_t)row * KD : Bup + (size_t)(row - 64) * KD)
                : Bbase + (size_t)row * KD;
            breg[buf][j] = *(const float4*)(src + koff + (idx & 15) * 4);
        }
    };
    auto stsQ = [&](int s, int q, int buf) {
        char* b16 = smem + s * STAGE_SZ + OFF_B;
#pragma unroll
        for (int j = 0; j < 2; ++j) {
            const int idx = j * 256 + tid;
            *(uint2*)(b16 + (q * 32 + (idx >> 4)) * ROWB + (idx & 15) * 8) =
                make_uint2(pack_h2(breg[buf][j].x, breg[buf][j].y),
                           pack_h2(breg[buf][j].z, breg[buf][j].w));
        }
    };
    auto issueA = [&](int c, int s) {
        const uint32_t base = sb + s * STAGE_SZ;
        const int koff = c * BK;
#pragma unroll
        for (int j = 0; j < 4; ++j)
            cpa16(base + doffA + j * 32 * ROWB, Aptr + (size_t)j * 32 * KD + koff);
        CPA_COMMIT();
    };

    float acc[4][4][4];
#pragma unroll
    for (int mt = 0; mt < 4; ++mt)
#pragma unroll
        for (int nt = 0; nt < 4; ++nt)
#pragma unroll
            for (int r = 0; r < 4; ++r) acc[mt][nt][r] = 0.0f;

    const uint32_t lmoff = (uint32_t)((wm * 64 + (lane & 7) + ((lane >> 3) & 1) * 8) * ROWB
                                      + (lane >> 4) * 16);
    const uint32_t lbofr = (uint32_t)((wn * 32 + ((lane >> 4) & 1) * 8 + (lane & 7)) * ROWB
                                      + ((lane >> 3) & 1) * 16);

    // one ks step: 4 A-ldm4 + 2 B-ldm4 + 16 mma
    auto do_ks = [&](uint32_t As, uint32_t Bs, int ks) {
        uint32_t a[4][4];
#pragma unroll
        for (int mt = 0; mt < 4; ++mt)
            ldm4(a[mt], As + lmoff + mt * 16 * ROWB + ks * 32);
        uint32_t b[4][2];
#pragma unroll
        for (int ntp = 0; ntp < 2; ++ntp) {
            uint32_t r[4];
            ldm4(r, Bs + lbofr + ntp * 16 * ROWB + ks * 32);
            b[2 * ntp][0] = r[0];     b[2 * ntp][1] = r[1];
            b[2 * ntp + 1][0] = r[2]; b[2 * ntp + 1][1] = r[3];
        }
#pragma unroll
        for (int mt = 0; mt < 4; ++mt)
#pragma unroll
            for (int nt = 0; nt < 4; ++nt)
                mma16816(acc[mt][nt], a[mt], b[nt]);
    };

    // prologue: chunk 0 into stage 0; prefetch (1, q0)
    issueA(0, 0);
    ldQ(0, 0, 0); stsQ(0, 0, 0);
    ldQ(0, 1, 1); stsQ(0, 1, 1);
    ldQ(0, 2, 0); stsQ(0, 2, 0);
    ldQ(0, 3, 1); stsQ(0, 3, 1);
    ldQ(1, 0, 0);

#pragma unroll 1
    for (int c = 0; c < NC; ++c) {
        const int s = c & 1;
        CPA_WAIT0();
        __syncthreads();

        const bool m1 = (c + 1 < NC);
        const uint32_t As = sb + s * STAGE_SZ;
        const uint32_t Bs = As + OFF_B;

        if (m1) { issueA(c + 1, s ^ 1); stsQ(s ^ 1, 0, 0); ldQ(c + 1, 1, 1); }
        do_ks(As, Bs, 0);
        if (m1) { stsQ(s ^ 1, 1, 1); ldQ(c + 1, 2, 0); }
        do_ks(As, Bs, 1);
        if (m1) { stsQ(s ^ 1, 2, 0); ldQ(c + 1, 3, 1); }
        do_ks(As, Bs, 2);
        if (m1) stsQ(s ^ 1, 3, 1);
        if (c + 2 < NC) ldQ(c + 2, 0, 0);
        do_ks(As, Bs, 3);
    }

    // ---------------- epilogue ----------------
    if (MODE == 1) {
        // wn 0,1 = gate (cols wn*32..), wn 2,3 = up (cols (wn-2)*32..)
        constexpr int XP = 65;
        float* xg = (float*)smem;
        __syncthreads();
        if (wn < 2) {
#pragma unroll
            for (int mt = 0; mt < 4; ++mt) {
                const int r0 = wm * 64 + mt * 16 + (lane >> 2);
#pragma unroll
                for (int nt = 0; nt < 4; ++nt) {
                    const int c0 = wn * 32 + nt * 8 + (lane & 3) * 2;
                    xg[r0 * XP + c0]           = acc[mt][nt][0];
                    xg[r0 * XP + c0 + 1]       = acc[mt][nt][1];
                    xg[(r0 + 8) * XP + c0]     = acc[mt][nt][2];
                    xg[(r0 + 8) * XP + c0 + 1] = acc[mt][nt][3];
                }
            }
        }
        __syncthreads();
        if (wn >= 2) {
#pragma unroll
            for (int mt = 0; mt < 4; ++mt) {
                const int rl = wm * 64 + mt * 16 + (lane >> 2);
                const int grow0 = tile_m * BM + rl;
#pragma unroll
                for (int nt = 0; nt < 4; ++nt) {
                    const int c0 = (wn - 2) * 32 + nt * 8 + (lane & 3) * 2;
                    float g0 = xg[rl * XP + c0];
                    float g1 = xg[rl * XP + c0 + 1];
                    float g2 = xg[(rl + 8) * XP + c0];
                    float g3 = xg[(rl + 8) * XP + c0 + 1];
                    float o0 = acc[mt][nt][0] * g0 / (1.0f + expf(-g0));
                    float o1 = acc[mt][nt][1] * g1 / (1.0f + expf(-g1));
                    float o2 = acc[mt][nt][2] * g2 / (1.0f + expf(-g2));
                    float o3 = acc[mt][nt][3] * g3 / (1.0f + expf(-g3));
                    *(uint32_t*)(g_act + (size_t)grow0 * F_DIM + tile_n * 64 + c0)       = pack_h2(o0, o1);
                    *(uint32_t*)(g_act + (size_t)(grow0 + 8) * F_DIM + tile_n * 64 + c0) = pack_h2(o2, o3);
                }
            }
        }
    } else {
#pragma unroll
        for (int mt = 0; mt < 4; ++mt) {
            const int r0 = tile_m * BM + wm * 64 + mt * 16 + (lane >> 2);
            const int t0 = g_tok[r0];
            const int t1 = g_tok[r0 + 8];
            const float w0 = g_wt[r0];
            const float w1 = g_wt[r0 + 8];
#pragma unroll
            for (int nt = 0; nt < 4; ++nt) {
                const int c0 = tile_n * BM + wn * 32 + nt * 8 + (lane & 3) * 2;
                if (t0 >= 0) {
                    atomicAdd(out + (size_t)t0 * H_DIM + c0,     w0 * acc[mt][nt][0]);
                    atomicAdd(out + (size_t)t0 * H_DIM + c0 + 1, w0 * acc[mt][nt][1]);
                }
                if (t1 >= 0) {
                    atomicAdd(out + (size_t)t1 * H_DIM + c0,     w1 * acc[mt][nt][2]);
                    atomicAdd(out + (size_t)t1 * H_DIM + c0 + 1, w1 * acc[mt][nt][3]);
                }
            }
        }
    }
}

// ---------------- launch ----------------
extern "C" void kernel_launch(void* const* d_in, const int* in_sizes, int n_in,
                              void* d_out, int out_size) {
    const float* X   = (const float*)d_in[0];
    const float* rw  = (const float*)d_in[1];
    const int*   sel = (const int*)  d_in[2];
    const float* W1  = (const float*)d_in[3];
    const float* W2  = (const float*)d_in[4];
    float* out = (float*)d_out;

    constexpr int SMEM = 2 * STAGE_SZ;         // 73728
    static int cfg = 0;
    if (!cfg) {
        cudaFuncSetAttribute(k_gemm<1>, cudaFuncAttributeMaxDynamicSharedMemorySize, SMEM);
        cudaFuncSetAttribute(k_gemm<2>, cudaFuncAttributeMaxDynamicSharedMemorySize, SMEM);
        cfg = 1;
    }

    k_zero<<<256, 256>>>(out);
    k_route<<<1, 1024>>>(sel, rw);
    k_gather<<<MAXROWS, 256>>>(X);

    dim3 g1(MAXTILES, F_DIM / 64);       // 40 x 88, tile_m fast
    k_gemm<1><<<g1, 256, SMEM>>>(W1, nullptr);

    dim3 g2(MAXTILES, H_DIM / BM, 2);    // 40 x 16 x 2 (split-K)
    k_gemm<2><<<g2, 256, SMEM>>>(W2, out);
}

// round 16
// speedup vs baseline: 1.3045x; 1.3045x over previous
#include <cuda_runtime.h>
#include <cuda_fp16.h>
#include <cstdint>

// ---------------- problem constants ----------------
#define T_TOK 2048
#define H_DIM 2048
#define F_DIM 5632
#define E_NUM 8
#define K_TOP 2
#define F2    (2 * F_DIM)

// ---------------- tiling ----------------
#define BM 128
#define BK 64
#define ROWB 144                      // fp16 row pitch bytes (72 halves)
#define TILE16 (BM * ROWB)            // 18432
#define STAGE_SZ (2 * TILE16)         // A16 + B16 = 36864
#define NSTAGE 3
#define OFF_B TILE16
#define MAXROWS  5120
#define MAXTILES 40

// ---------------- device scratch ----------------
__device__ __half g_xg [(size_t)MAXROWS * H_DIM];
__device__ __half g_act[(size_t)MAXROWS * F_DIM];
__device__ int   g_tok[MAXROWS];
__device__ float g_wt [MAXROWS];
__device__ int   g_tile_expert[MAXTILES];

// ---------------- helpers ----------------
__device__ __forceinline__ uint32_t smem_u32(const void* p) {
    uint32_t a;
    asm("{ .reg .u64 t; cvta.to.shared.u64 t, %1; cvt.u32.u64 %0, t; }" : "=r"(a) : "l"(p));
    return a;
}
__device__ __forceinline__ void cpa16(uint32_t dst, const void* src) {
    asm volatile("cp.async.cg.shared.global [%0], [%1], 16;" :: "r"(dst), "l"(src));
}
#define CPA_COMMIT() asm volatile("cp.async.commit_group;" ::: "memory")
#define CPA_WAIT0()  asm volatile("cp.async.wait_group 0;" ::: "memory")
#define CPA_WAIT1()  asm volatile("cp.async.wait_group 1;" ::: "memory")

__device__ __forceinline__ void ldm4(uint32_t* r, uint32_t addr) {
    asm volatile("ldmatrix.sync.aligned.m8n8.x4.shared.b16 {%0,%1,%2,%3}, [%4];"
                 : "=r"(r[0]), "=r"(r[1]), "=r"(r[2]), "=r"(r[3]) : "r"(addr));
}
__device__ __forceinline__ void mma16816(float* d, const uint32_t* a, const uint32_t* b) {
    asm("mma.sync.aligned.m16n8k16.row.col.f32.f16.f16.f32 "
        "{%0,%1,%2,%3}, {%4,%5,%6,%7}, {%8,%9}, {%0,%1,%2,%3};\n"
        : "+f"(d[0]), "+f"(d[1]), "+f"(d[2]), "+f"(d[3])
        : "r"(a[0]), "r"(a[1]), "r"(a[2]), "r"(a[3]),
          "r"(b[0]), "r"(b[1]));
}
__device__ __forceinline__ uint32_t pack_h2(float a, float b) {
    __half2 h = __floats2half2_rn(a, b);
    return *(uint32_t*)&h;
}

// ---------------- routing ----------------
__global__ void k_zero(float* __restrict__ out) {
    int tid = blockIdx.x * blockDim.x + threadIdx.x;
    int nt  = gridDim.x * blockDim.x;
    for (int i = tid; i < T_TOK * H_DIM; i += nt) out[i] = 0.0f;
}
__global__ void k_route(const int* __restrict__ sel, const float* __restrict__ rw) {
    __shared__ int cnt[E_NUM];
    __shared__ int cur[E_NUM];
    const int tid = threadIdx.x;
    if (tid < E_NUM) cnt[tid] = 0;
    for (int i = tid; i < MAXROWS; i += blockDim.x) { g_tok[i] = -1; g_wt[i] = 0.0f; }
    __syncthreads();
    for (int i = tid; i < T_TOK * K_TOP; i += blockDim.x) atomicAdd(&cnt[sel[i]], 1);
    __syncthreads();
    if (tid == 0) {
        for (int t = 0; t < MAXTILES; ++t) g_tile_expert[t] = -1;
        int off = 0;
        for (int e = 0; e < E_NUM; ++e) {
            cur[e] = off;
            int tiles = (cnt[e] + BM - 1) / BM;
            for (int j = 0; j < tiles; ++j) g_tile_expert[off / BM + j] = e;
            off += tiles * BM;
        }
    }
    __syncthreads();
    for (int i = tid; i < T_TOK * K_TOP; i += blockDim.x) {
        int e = sel[i];
        int pos = atomicAdd(&cur[e], 1);
        g_tok[pos] = i / K_TOP;
        g_wt[pos]  = rw[i];
    }
}
__global__ void k_gather(const float* __restrict__ X) {
    const int row = blockIdx.x;
    if (g_tile_expert[row >> 7] < 0) return;
    const int tok = g_tok[row];
    uint2* dst = (uint2*)(g_xg + (size_t)row * H_DIM);
    if (tok >= 0) {
        const float4* src = (const float4*)(X + (size_t)tok * H_DIM);
        for (int i = threadIdx.x; i < H_DIM / 4; i += blockDim.x) {
            float4 v = src[i];
            dst[i] = make_uint2(pack_h2(v.x, v.y), pack_h2(v.z, v.w));
        }
    } else {
        for (int i = threadIdx.x; i < H_DIM / 4; i += blockDim.x)
            dst[i] = make_uint2(0u, 0u);
    }
}

// ---------------- fp16 tensor GEMM: 128 thr, 4 warps of 64x64, 3-stage ----------------
// A via cp.async 2 chunks ahead (wait_group 1). B via half-chunk LDG fp32 -> reg
// -> fp16 STS one chunk ahead. Inner loop: software-pipelined LDSM+HMMA.
// grid: x = tile_m (fast, L2 B reuse), y = tile_n, z = K-split (MODE 2)
template <int MODE>
__global__ void __launch_bounds__(128, 2)
k_gemm(const float* __restrict__ W, float* __restrict__ out) {
    constexpr int KD     = (MODE == 1) ? H_DIM : F_DIM;
    constexpr int KSPLIT = (MODE == 1) ? 1 : 2;
    constexpr int NC     = KD / BK / KSPLIT;   // 32 or 44

    const int tile_m = blockIdx.x;
    const int tile_n = blockIdx.y;
    const int koff0  = (MODE == 2) ? (int)blockIdx.z * (KD / KSPLIT) : 0;
    const int e = g_tile_expert[tile_m];
    if (e < 0) return;

    extern __shared__ char smem[];
    const uint32_t sb = smem_u32(smem);

    const int tid  = threadIdx.x;
    const int lane = tid & 31;
    const int warp = tid >> 5;
    const int wm   = warp & 1;
    const int wn   = warp >> 1;

    // ---- A cp.async: row = j*16 + (tid>>3), q = tid&7
    const __half* Aptr = (((MODE == 1) ? g_xg : g_act) + (size_t)tile_m * BM * KD)
                         + (size_t)(tid >> 3) * KD + (tid & 7) * 8 + koff0;
    const uint32_t doffA = (uint32_t)((tid >> 3) * ROWB + (tid & 7) * 16);

    // ---- B fp32 LDG (half-chunk staging)
    const int br = tid >> 4;                   // 0..7
    const int bq = tid & 15;
    const float* Bbase;
    const float* Bup = nullptr;
    if (MODE == 1) {
        Bbase = W + (size_t)e * F2 * H_DIM + (size_t)tile_n * 64 * H_DIM;
        Bup   = Bbase + (size_t)F_DIM * H_DIM;
    } else {
        Bbase = W + (size_t)e * H_DIM * F_DIM + (size_t)tile_n * BM * F_DIM;
    }
    const uint32_t doffB = (uint32_t)(br * ROWB + bq * 8);

    float4 breg[8];
    auto ldB_half = [&](int c, int h) {
        const int koff = koff0 + c * BK + bq * 4;
#pragma unroll
        for (int jj = 0; jj < 8; ++jj) {
            const int row = (h * 8 + jj) * 8 + br;
            const float* src = (MODE == 1)
                ? ((h == 0) ? Bbase + (size_t)row * KD : Bup + (size_t)(row - 64) * KD)
                : Bbase + (size_t)row * KD;
            breg[jj] = *(const float4*)(src + koff);
        }
    };
    auto stsB_half = [&](int s, int h) {
        char* b16 = smem + s * STAGE_SZ + OFF_B;
#pragma unroll
        for (int jj = 0; jj < 8; ++jj)
            *(uint2*)(b16 + doffB + (h * 8 + jj) * 8 * ROWB) =
                make_uint2(pack_h2(breg[jj].x, breg[jj].y), pack_h2(breg[jj].z, breg[jj].w));
    };
    auto issueA = [&](int c, int s) {
        const uint32_t base = sb + s * STAGE_SZ;
        const int koff = c * BK;
#pragma unroll
        for (int j = 0; j < 8; ++j)
            cpa16(base + doffA + j * 16 * ROWB, Aptr + (size_t)j * 16 * KD + koff);
        CPA_COMMIT();
    };

    float acc[4][8][4];
#pragma unroll
    for (int mt = 0; mt < 4; ++mt)
#pragma unroll
        for (int nt = 0; nt < 8; ++nt)
#pragma unroll
            for (int r = 0; r < 4; ++r) acc[mt][nt][r] = 0.0f;

    const uint32_t lmoff = (uint32_t)((wm * 64 + (lane & 7) + ((lane >> 3) & 1) * 8) * ROWB
                                      + (lane >> 4) * 16);
    const uint32_t lbofr = (uint32_t)((wn * 64 + ((lane >> 4) & 1) * 8 + (lane & 7)) * ROWB
                                      + ((lane >> 3) & 1) * 16);

    // double-buffered mma fragments
    uint32_t afr[2][4][4];
    uint32_t bfr[2][8][2];
    auto load_frag = [&](uint32_t As, uint32_t Bs, int ks, int buf) {
#pragma unroll
        for (int mt = 0; mt < 4; ++mt)
            ldm4(afr[buf][mt], As + lmoff + mt * 16 * ROWB + ks * 32);
#pragma unroll
        for (int ntp = 0; ntp < 4; ++ntp) {
            uint32_t r[4];
            ldm4(r, Bs + lbofr + ntp * 16 * ROWB + ks * 32);
            bfr[buf][2 * ntp][0] = r[0];     bfr[buf][2 * ntp][1] = r[1];
            bfr[buf][2 * ntp + 1][0] = r[2]; bfr[buf][2 * ntp + 1][1] = r[3];
        }
    };
    auto mma_all = [&](int buf) {
#pragma unroll
        for (int mt = 0; mt < 4; ++mt)
#pragma unroll
            for (int nt = 0; nt < 8; ++nt)
                mma16816(acc[mt][nt], afr[buf][mt], bfr[buf][nt]);
    };

    // prologue: A chunks 0,1 in flight; B chunk 0 fully staged; prefetch (1,h0)
    issueA(0, 0);
    ldB_half(0, 0); stsB_half(0, 0);
    ldB_half(0, 1); stsB_half(0, 1);
    if (NC > 1) issueA(1, 1);
    ldB_half(1, 0);

    int s = 0, s1 = 1, s2 = 2;
#pragma unroll 1
    for (int c = 0; c < NC; ++c) {
        if (c < NC - 1) CPA_WAIT1(); else CPA_WAIT0();
        __syncthreads();

        const bool more1 = (c + 1 < NC);
        if (more1) {
            stsB_half(s1, 0);                  // (c+1, h0) staged last chunk
            ldB_half(c + 1, 1);                // LDG (c+1, h1)
        }
        if (c + 2 < NC) issueA(c + 2, s2);     // A two chunks ahead

        const uint32_t As = sb + s * STAGE_SZ;
        const uint32_t Bs = As + OFF_B;

        load_frag(As, Bs, 0, 0);
        load_frag(As, Bs, 1, 1);
        mma_all(0);
        load_frag(As, Bs, 2, 0);
        mma_all(1);
        if (more1) stsB_half(s1, 1);           // (c+1, h1)
        if (c + 2 < NC) ldB_half(c + 2, 0);    // LDG (c+2, h0)
        load_frag(As, Bs, 3, 1);
        mma_all(0);
        mma_all(1);

        const int t = s; s = s1; s1 = s2; s2 = t;
    }

    // ---------------- epilogue ----------------
    if (MODE == 1) {
        constexpr int XP = 65;
        float* xg = (float*)smem;
        __syncthreads();
        if (wn == 0) {
#pragma unroll
            for (int mt = 0; mt < 4; ++mt) {
                const int r0 = wm * 64 + mt * 16 + (lane >> 2);
#pragma unroll
                for (int nt = 0; nt < 8; ++nt) {
                    const int c0 = nt * 8 + (lane & 3) * 2;
                    xg[r0 * XP + c0]           = acc[mt][nt][0];
                    xg[r0 * XP + c0 + 1]       = acc[mt][nt][1];
                    xg[(r0 + 8) * XP + c0]     = acc[mt][nt][2];
                    xg[(r0 + 8) * XP + c0 + 1] = acc[mt][nt][3];
                }
            }
        }
        __syncthreads();
        if (wn == 1) {
#pragma unroll
            for (int mt = 0; mt < 4; ++mt) {
                const int rl = wm * 64 + mt * 16 + (lane >> 2);
                const int grow0 = tile_m * BM + rl;
#pragma unroll
                for (int nt = 0; nt < 8; ++nt) {
                    const int c0 = nt * 8 + (lane & 3) * 2;
                    float g0 = xg[rl * XP + c0];
                    float g1 = xg[rl * XP + c0 + 1];
                    float g2 = xg[(rl + 8) * XP + c0];
                    float g3 = xg[(rl + 8) * XP + c0 + 1];
                    float o0 = acc[mt][nt][0] * g0 / (1.0f + expf(-g0));
                    float o1 = acc[mt][nt][1] * g1 / (1.0f + expf(-g1));
                    float o2 = acc[mt][nt][2] * g2 / (1.0f + expf(-g2));
                    float o3 = acc[mt][nt][3] * g3 / (1.0f + expf(-g3));
                    *(uint32_t*)(g_act + (size_t)grow0 * F_DIM + tile_n * 64 + c0)       = pack_h2(o0, o1);
                    *(uint32_t*)(g_act + (size_t)(grow0 + 8) * F_DIM + tile_n * 64 + c0) = pack_h2(o2, o3);
                }
            }
        }
    } else {
#pragma unroll
        for (int mt = 0; mt < 4; ++mt) {
            const int r0 = tile_m * BM + wm * 64 + mt * 16 + (lane >> 2);
            const int t0 = g_tok[r0];
            const int t1 = g_tok[r0 + 8];
            const float w0 = g_wt[r0];
            const float w1 = g_wt[r0 + 8];
#pragma unroll
            for (int nt = 0; nt < 8; ++nt) {
                const int c0 = tile_n * BM + wn * 64 + nt * 8 + (lane & 3) * 2;
                if (t0 >= 0) {
                    atomicAdd(out + (size_t)t0 * H_DIM + c0,     w0 * acc[mt][nt][0]);
                    atomicAdd(out + (size_t)t0 * H_DIM + c0 + 1, w0 * acc[mt][nt][1]);
                }
                if (t1 >= 0) {
                    atomicAdd(out + (size_t)t1 * H_DIM + c0,     w1 * acc[mt][nt][2]);
                    atomicAdd(out + (size_t)t1 * H_DIM + c0 + 1, w1 * acc[mt][nt][3]);
                }
            }
        }
    }
}

// ---------------- launch ----------------
extern "C" void kernel_launch(void* const* d_in, const int* in_sizes, int n_in,
                              void* d_out, int out_size) {
    const float* X   = (const float*)d_in[0];
    const float* rw  = (const float*)d_in[1];
    const int*   sel = (const int*)  d_in[2];
    const float* W1  = (const float*)d_in[3];
    const float* W2  = (const float*)d_in[4];
    float* out = (float*)d_out;

    constexpr int SMEM = NSTAGE * STAGE_SZ;    // 110592
    static int cfg = 0;
    if (!cfg) {
        cudaFuncSetAttribute(k_gemm<1>, cudaFuncAttributeMaxDynamicSharedMemorySize, SMEM);
        cudaFuncSetAttribute(k_gemm<2>, cudaFuncAttributeMaxDynamicSharedMemorySize, SMEM);
        cfg = 1;
    }

    k_zero<<<256, 256>>>(out);
    k_route<<<1, 1024>>>(sel, rw);
    k_gather<<<MAXROWS, 256>>>(X);

    dim3 g1(MAXTILES, F_DIM / 64);       // 40 x 88, tile_m fast
    k_gemm<1><<<g1, 128, SMEM>>>(W1, nullptr);

    dim3 g2(MAXTILES, H_DIM / BM, 2);    // 40 x 16 x 2 (split-K)
    k_gemm<2><<<g2, 128, SMEM>>>(W2, out);
}